// round 12
// baseline (speedup 1.0000x reference)
#include <cuda_runtime.h>
#include <math.h>

#define VOLD   256
#define NGAUSS 4000
// Tile shape 8 x 8 x 16 (x,y,z); block per tile, thread per z-quad (4 voxels).
#define TSX 8
#define TSY 8
#define TSZ 16
#define NTX 32
#define NTY 32
#define NTZ 16
#define NTILES (NTX * NTY * NTZ)      // 16384
#define CAP    32
#define SLICE  32                     // wx[8] wy[8] wz[16]

// ---------------------------------------------------------------------------
// Static device scratch. Zeroed at module load; gather self-cleans g_cnt each
// launch, so the invariant holds across correctness run, capture, and replays.
// g_ids needs no cleaning: only entries [0, cnt) are ever read.
// ---------------------------------------------------------------------------
__device__ int g_cnt[NTILES];
__device__ int g_ids[NTILES * CAP];   // 2 MB

// ---------------------------------------------------------------------------
// Kernel 1: binning only. Block per Gaussian; threads 0..2 compute the
// per-axis tile bbox (no exps), then thread-per-pair atomic + id store.
// ---------------------------------------------------------------------------
__global__ __launch_bounds__(128) void prep_kernel(
    const float* __restrict__ centers,
    const float* __restrict__ sigmas)
{
    const int g = blockIdx.x;
    const int t = threadIdx.x;

    __shared__ int s_tmin[3], s_tn[3];

    if (t < 3) {
        const float sig = sigmas[g];
        const float cn  = centers[3 * g + t];
        const float cv  = cn * 255.0f;
        const float cut = 3.0f * sig * 255.0f;

        const float minf = fmaxf(cv - cut, 0.0f);
        const float maxf = fminf(cv + cut, 255.0f);
        const int   mini = (int)floorf(minf);
        const int   maxi = min((int)floorf(maxf) + 1, VOLD);   // exclusive

        const int shf  = (t == 2) ? 4 : 3;
        const int tmin = mini >> shf;
        const int tmax = (maxi - 1) >> shf;
        s_tmin[t] = tmin;
        s_tn[t]   = tmax - tmin + 1;
    }
    __syncthreads();

    const int nx = s_tn[0], ny = s_tn[1], nz = s_tn[2];
    const int x0 = s_tmin[0], y0 = s_tmin[1], z0 = s_tmin[2];
    const int total = nx * ny * nz;          // <= ~48

    for (int i = t; i < total; i += 128) {
        const int iz = i % nz;
        const int r  = i / nz;
        const int iy = r % ny;
        const int ix = r / ny;
        const int tile = ((x0 + ix) * NTY + (y0 + iy)) * NTZ + (z0 + iz);

        const int slot = atomicAdd(&g_cnt[tile], 1);
        if (slot < CAP) g_ids[tile * CAP + slot] = g;
    }
}

// ---------------------------------------------------------------------------
// Kernel 2: gather, BLOCK per 8x8x16 tile (256 threads). Weight phase: warp w
// computes all 32 weights of pairs w, w+8, ... in parallel (lane = weight
// index). FMA phase: thread owns one 4-voxel z-quad (4 accumulators only).
// ---------------------------------------------------------------------------
__global__ __launch_bounds__(256, 6) void gather_kernel(
    const float* __restrict__ centers,
    const float* __restrict__ sigmas,
    const float* __restrict__ intens,
    float* __restrict__ vol)
{
    const int tile = blockIdx.x;
    const int t    = threadIdx.x;
    const int warp = t >> 5;
    const int lane = t & 31;

    __shared__ __align__(16) float sw[CAP][SLICE];   // 4 KB
    __shared__ int s_cnt;

    if (t == 0) {
        s_cnt = min(g_cnt[tile], CAP);
        g_cnt[tile] = 0;               // restore invariant for next launch
    }
    __syncthreads();
    const int cnt = s_cnt;

    const int tzi = tile & (NTZ - 1);
    const int tyi = (tile >> 4) & (NTY - 1);
    const int txi = tile >> 9;

    // ---- Weight phase: warp per pair, lane per weight ----
    // lane 0-7: wx[o], 8-15: wy[o], 16-31: wz[o]
    {
        const int axis = min(lane >> 3, 2);
        const int o    = lane - (axis << 3);
        const int tb   = (axis == 0) ? txi * TSX
                       : ((axis == 1) ? tyi * TSY : tzi * TSZ);
        const int idxv = tb + o;
        const float pos = (float)idxv * (1.0f / 255.0f);

        for (int p = warp; p < cnt; p += 8) {
            const int gid   = g_ids[tile * CAP + p];   // warp-uniform load
            const float sig = sigmas[gid];
            const float c   = centers[3 * gid + axis];
            const float I   = intens[gid];

            const float cv  = c * 255.0f;
            const float cut = 3.0f * sig * 255.0f;
            const float minf = fmaxf(cv - cut, 0.0f);
            const float maxf = fminf(cv + cut, 255.0f);
            const int   mini = (int)floorf(minf);
            const int   maxi = min((int)floorf(maxf) + 1, VOLD);

            float w = 0.0f;
            if (idxv >= mini && idxv < maxi) {
                const float d = pos - c;
                const float a = __fdividef(0.5f, sig * sig);
                w = __expf(-d * d * a);
            }
            if (axis == 0) w *= I;
            sw[p][lane] = w;
        }
    }
    __syncthreads();

    // ---- FMA phase: thread per z-quad ----
    // t -> (x, y, zq): x = t>>5, y = (t>>2)&7, zq = t&3
    const int x  = t >> 5;
    const int y  = (t >> 2) & 7;
    const int zq = t & 3;

    float a0 = 0.f, a1 = 0.f, a2 = 0.f, a3 = 0.f;

#pragma unroll 4
    for (int p = 0; p < cnt; ++p) {
        const float f = sw[p][x] * sw[p][8 + y];
        const float4 wz = *(const float4*)&sw[p][16 + 4 * zq];
        a0 = fmaf(f, wz.x, a0);
        a1 = fmaf(f, wz.y, a1);
        a2 = fmaf(f, wz.z, a2);
        a3 = fmaf(f, wz.w, a3);
    }

    float* out = vol + ((size_t)(txi * TSX + x) * VOLD + (tyi * TSY + y)) * VOLD
                     + tzi * TSZ + 4 * zq;
    *(float4*)out = make_float4(a0, a1, a2, a3);
}

// ---------------------------------------------------------------------------
extern "C" void kernel_launch(void* const* d_in, const int* in_sizes, int n_in,
                              void* d_out, int out_size) {
    const float* centers = (const float*)d_in[0];
    const float* sigmas  = (const float*)d_in[1];
    const float* intens  = (const float*)d_in[2];
    float* vol = (float*)d_out;

    prep_kernel<<<NGAUSS, 128>>>(centers, sigmas);
    gather_kernel<<<NTILES, 256>>>(centers, sigmas, intens, vol);
}

// round 13
// speedup vs baseline: 3.1975x; 3.1975x over previous
#include <cuda_runtime.h>
#include <math.h>

#define VOLD   256
#define NGAUSS 4000
// Tile shape 8 x 8 x 16 (x,y,z); warp per tile, 4 tiles per 128-thread block.
#define TSX 8
#define TSY 8
#define TSZ 16
#define NTX 32
#define NTY 32
#define NTZ 16
#define NTILES (NTX * NTY * NTZ)      // 16384
#define CAP    32
#define SLICE  32                     // wx[8] wy[8] wz[16]

// ---------------------------------------------------------------------------
// Static device scratch. Zeroed at module load; gather self-cleans g_cnt each
// launch, so the invariant holds across correctness run, capture, and replays.
// g_ids needs no cleaning: only entries [0, cnt) are ever read.
// ---------------------------------------------------------------------------
__device__ int g_cnt[NTILES];
__device__ int g_ids[NTILES * CAP];   // 2 MB

// ---------------------------------------------------------------------------
// Kernel 1: binning only. Block per Gaussian; threads 0..2 compute the
// per-axis tile bbox (no exps), then thread-per-pair atomic + id store.
// ---------------------------------------------------------------------------
__global__ __launch_bounds__(128) void prep_kernel(
    const float* __restrict__ centers,
    const float* __restrict__ sigmas)
{
    const int g = blockIdx.x;
    const int t = threadIdx.x;

    __shared__ int s_tmin[3], s_tn[3];

    if (t < 3) {
        const float sig = sigmas[g];
        const float cn  = centers[3 * g + t];
        const float cv  = cn * 255.0f;
        const float cut = 3.0f * sig * 255.0f;

        const float minf = fmaxf(cv - cut, 0.0f);
        const float maxf = fminf(cv + cut, 255.0f);
        const int   mini = (int)floorf(minf);
        const int   maxi = min((int)floorf(maxf) + 1, VOLD);   // exclusive

        const int shf  = (t == 2) ? 4 : 3;
        const int tmin = mini >> shf;
        const int tmax = (maxi - 1) >> shf;
        s_tmin[t] = tmin;
        s_tn[t]   = tmax - tmin + 1;
    }
    __syncthreads();

    const int nx = s_tn[0], ny = s_tn[1], nz = s_tn[2];
    const int x0 = s_tmin[0], y0 = s_tmin[1], z0 = s_tmin[2];
    const int total = nx * ny * nz;          // <= ~48

    for (int i = t; i < total; i += 128) {
        const int iz = i % nz;
        const int r  = i / nz;
        const int iy = r % ny;
        const int ix = r / ny;
        const int tile = ((x0 + ix) * NTY + (y0 + iy)) * NTZ + (z0 + iz);

        const int slot = atomicAdd(&g_cnt[tile], 1);
        if (slot < CAP) g_ids[tile * CAP + slot] = g;
    }
}

// ---------------------------------------------------------------------------
// Kernel 2: gather, warp per 8x8x16 tile (4 per 128-thread block).
// Phase 1: lane p derives pair p's params in parallel -> shared.
// Phase 2: weight loop (LDS-broadcast params, no shuffles, pipelined).
// Phase 3: FMA in two z-half passes (16 accumulators) -> 8 float4 stores.
// ---------------------------------------------------------------------------
__global__ __launch_bounds__(128) void gather_kernel(
    const float* __restrict__ centers,
    const float* __restrict__ sigmas,
    const float* __restrict__ intens,
    float* __restrict__ vol)
{
    const int warp = threadIdx.x >> 5;
    const int lane = threadIdx.x & 31;
    const int tile = blockIdx.x * 4 + warp;

    __shared__ __align__(16) float s_w[4][CAP * SLICE];    // 16 KB
    __shared__ float s_par[4][CAP][6];                     // 3 KB

    const int cnt = min(g_cnt[tile], CAP);

    // Phase 1: per-lane param derivation (parallel, full MLP)
    if (lane < cnt) {
        const int gid = g_ids[tile * CAP + lane];
        const float sig = sigmas[gid];
        s_par[warp][lane][0] = centers[3 * gid + 0];
        s_par[warp][lane][1] = centers[3 * gid + 1];
        s_par[warp][lane][2] = centers[3 * gid + 2];
        s_par[warp][lane][3] = __fdividef(0.5f, sig * sig);
        s_par[warp][lane][4] = 3.0f * sig * 255.0f;
        s_par[warp][lane][5] = intens[gid];
    }
    if (lane == 0) g_cnt[tile] = 0;       // restore invariant for next launch
    __syncwarp();

    const int tzi = tile & (NTZ - 1);
    const int tyi = (tile >> 4) & (NTY - 1);
    const int txi = tile >> 9;

    // Phase 2: weight loop. Lanes 0-7 wx, 8-15 wy, 16-31 wz.
    {
        const int axis = min(lane >> 3, 2);
        const int o    = lane - (axis << 3);
        const int tb   = (axis == 0) ? txi * TSX
                       : ((axis == 1) ? tyi * TSY : tzi * TSZ);
        const int idxv = tb + o;
        const float pos = (float)idxv * (1.0f / 255.0f);

#pragma unroll 4
        for (int p = 0; p < cnt; ++p) {
            const float c   = s_par[warp][p][axis];
            const float a   = s_par[warp][p][3];
            const float cut = s_par[warp][p][4];

            const float cv  = c * 255.0f;
            const float minf = fmaxf(cv - cut, 0.0f);
            const float maxf = fminf(cv + cut, 255.0f);
            const int   mini = (int)floorf(minf);
            const int   maxi = min((int)floorf(maxf) + 1, VOLD);

            float w = 0.0f;
            if (idxv >= mini && idxv < maxi) {
                const float d = pos - c;
                w = __expf(-d * d * a);
            }
            if (axis == 0) w *= s_par[warp][p][5];
            s_w[warp][p * SLICE + lane] = w;
        }
    }
    __syncwarp();

    // Phase 3: FMA, two z-half passes. Lane owns rows (x0,y) and (x0+4,y).
    const int x0 = lane >> 3;             // 0..3
    const int y  = lane & 7;
    const float* __restrict__ swp = s_w[warp];

    float* outb = vol + ((size_t)(txi * TSX + x0) * VOLD + (tyi * TSY + y)) * VOLD
                      + tzi * TSZ;
    const size_t xstep = (size_t)4 * VOLD * VOLD;   // x0 -> x0+4

#pragma unroll
    for (int half = 0; half < 2; ++half) {
        float a0[8], a1[8];
#pragma unroll
        for (int i = 0; i < 8; ++i) { a0[i] = 0.f; a1[i] = 0.f; }

#pragma unroll 4
        for (int p = 0; p < cnt; ++p) {
            const float* s = swp + p * SLICE;
            const float wy = s[8 + y];
            const float f0 = s[x0] * wy;
            const float f1 = s[x0 + 4] * wy;
#pragma unroll
            for (int q = 0; q < 2; ++q) {
                const float4 wz = *(const float4*)(s + 16 + 8 * half + 4 * q);
                a0[4*q+0] = fmaf(f0, wz.x, a0[4*q+0]);
                a0[4*q+1] = fmaf(f0, wz.y, a0[4*q+1]);
                a0[4*q+2] = fmaf(f0, wz.z, a0[4*q+2]);
                a0[4*q+3] = fmaf(f0, wz.w, a0[4*q+3]);
                a1[4*q+0] = fmaf(f1, wz.x, a1[4*q+0]);
                a1[4*q+1] = fmaf(f1, wz.y, a1[4*q+1]);
                a1[4*q+2] = fmaf(f1, wz.z, a1[4*q+2]);
                a1[4*q+3] = fmaf(f1, wz.w, a1[4*q+3]);
            }
        }

        float* o0 = outb + 8 * half;
        float* o1 = outb + xstep + 8 * half;
#pragma unroll
        for (int q = 0; q < 2; ++q) {
            *(float4*)(o0 + 4 * q) = make_float4(a0[4*q+0], a0[4*q+1], a0[4*q+2], a0[4*q+3]);
            *(float4*)(o1 + 4 * q) = make_float4(a1[4*q+0], a1[4*q+1], a1[4*q+2], a1[4*q+3]);
        }
    }
}

// ---------------------------------------------------------------------------
extern "C" void kernel_launch(void* const* d_in, const int* in_sizes, int n_in,
                              void* d_out, int out_size) {
    const float* centers = (const float*)d_in[0];
    const float* sigmas  = (const float*)d_in[1];
    const float* intens  = (const float*)d_in[2];
    float* vol = (float*)d_out;

    prep_kernel<<<NGAUSS, 128>>>(centers, sigmas);
    gather_kernel<<<NTILES / 4, 128>>>(centers, sigmas, intens, vol);
}

// round 14
// speedup vs baseline: 4.9054x; 1.5341x over previous
#include <cuda_runtime.h>
#include <math.h>

#define VOLD   256
#define NGAUSS 4000
// Tile shape 8 x 8 x 16 (x,y,z); warp per tile, 4 tiles per 128-thread block.
#define TSX 8
#define TSY 8
#define TSZ 16
#define NTX 32
#define NTY 32
#define NTZ 16
#define NTILES (NTX * NTY * NTZ)      // 16384
#define CAP    32
#define SLICE  32                     // wx[8] wy[8] wz[16]

// ---------------------------------------------------------------------------
// Static device scratch. Zeroed at module load; gather self-cleans g_cnt each
// launch, so the invariant holds across correctness run, capture, and replays.
// g_ids needs no cleaning: only entries [0, cnt) are ever read.
// ---------------------------------------------------------------------------
__device__ int g_cnt[NTILES];
__device__ int g_ids[NTILES * CAP];   // 2 MB

// ---------------------------------------------------------------------------
// Kernel 1: binning only. Block per Gaussian; threads 0..2 compute the
// per-axis tile bbox (no exps), then thread-per-pair atomic + id store.
// ---------------------------------------------------------------------------
__global__ __launch_bounds__(128) void prep_kernel(
    const float* __restrict__ centers,
    const float* __restrict__ sigmas)
{
    const int g = blockIdx.x;
    const int t = threadIdx.x;

    __shared__ int s_tmin[3], s_tn[3];

    if (t < 3) {
        const float sig = sigmas[g];
        const float cn  = centers[3 * g + t];
        const float cv  = cn * 255.0f;
        const float cut = 3.0f * sig * 255.0f;

        const float minf = fmaxf(cv - cut, 0.0f);
        const float maxf = fminf(cv + cut, 255.0f);
        const int   mini = (int)floorf(minf);
        const int   maxi = min((int)floorf(maxf) + 1, VOLD);   // exclusive

        const int shf  = (t == 2) ? 4 : 3;
        const int tmin = mini >> shf;
        const int tmax = (maxi - 1) >> shf;
        s_tmin[t] = tmin;
        s_tn[t]   = tmax - tmin + 1;
    }
    __syncthreads();

    const int nx = s_tn[0], ny = s_tn[1], nz = s_tn[2];
    const int x0 = s_tmin[0], y0 = s_tmin[1], z0 = s_tmin[2];
    const int total = nx * ny * nz;          // <= ~48

    for (int i = t; i < total; i += 128) {
        const int iz = i % nz;
        const int r  = i / nz;
        const int iy = r % ny;
        const int ix = r / ny;
        const int tile = ((x0 + ix) * NTY + (y0 + iy)) * NTZ + (z0 + iz);

        const int slot = atomicAdd(&g_cnt[tile], 1);
        if (slot < CAP) g_ids[tile * CAP + slot] = g;
    }
}

// ---------------------------------------------------------------------------
// Kernel 2: gather, warp per 8x8x16 tile (4 per 128-thread block).
// Phase 1: lane p derives pair p's params in parallel -> shared.
// Phase 2: weight loop (LDS-broadcast params, no shuffles).
// Phase 3: FMA with lane = (y, zq); acc over all 8 x. Store: per x one
// STG.128 where each 4-lane group writes a contiguous 64B z-row ->
// 8 L1 lines per store instruction instead of 32.
// ---------------------------------------------------------------------------
__global__ __launch_bounds__(128, 8) void gather_kernel(
    const float* __restrict__ centers,
    const float* __restrict__ sigmas,
    const float* __restrict__ intens,
    float* __restrict__ vol)
{
    const int warp = threadIdx.x >> 5;
    const int lane = threadIdx.x & 31;
    const int tile = blockIdx.x * 4 + warp;

    __shared__ __align__(16) float s_w[4][CAP * SLICE];    // 16 KB
    __shared__ float s_par[4][CAP][6];                     // 3 KB

    const int cnt = min(g_cnt[tile], CAP);

    // Phase 1: per-lane param derivation (parallel, full MLP)
    if (lane < cnt) {
        const int gid = g_ids[tile * CAP + lane];
        const float sig = sigmas[gid];
        s_par[warp][lane][0] = centers[3 * gid + 0];
        s_par[warp][lane][1] = centers[3 * gid + 1];
        s_par[warp][lane][2] = centers[3 * gid + 2];
        s_par[warp][lane][3] = __fdividef(0.5f, sig * sig);
        s_par[warp][lane][4] = 3.0f * sig * 255.0f;
        s_par[warp][lane][5] = intens[gid];
    }
    if (lane == 0) g_cnt[tile] = 0;       // restore invariant for next launch
    __syncwarp();

    const int tzi = tile & (NTZ - 1);
    const int tyi = (tile >> 4) & (NTY - 1);
    const int txi = tile >> 9;

    // Phase 2: weight loop. Lanes 0-7 wx, 8-15 wy, 16-31 wz.
    {
        const int axis = min(lane >> 3, 2);
        const int o    = lane - (axis << 3);
        const int tb   = (axis == 0) ? txi * TSX
                       : ((axis == 1) ? tyi * TSY : tzi * TSZ);
        const int idxv = tb + o;
        const float pos = (float)idxv * (1.0f / 255.0f);

#pragma unroll 4
        for (int p = 0; p < cnt; ++p) {
            const float c   = s_par[warp][p][axis];
            const float a   = s_par[warp][p][3];
            const float cut = s_par[warp][p][4];

            const float cv  = c * 255.0f;
            const float minf = fmaxf(cv - cut, 0.0f);
            const float maxf = fminf(cv + cut, 255.0f);
            const int   mini = (int)floorf(minf);
            const int   maxi = min((int)floorf(maxf) + 1, VOLD);

            float w = 0.0f;
            if (idxv >= mini && idxv < maxi) {
                const float d = pos - c;
                w = __expf(-d * d * a);
            }
            if (axis == 0) w *= s_par[warp][p][5];
            s_w[warp][p * SLICE + lane] = w;
        }
    }
    __syncwarp();

    // Phase 3: FMA. Lane owns (y, zq); accumulate all 8 x slabs.
    const int y  = lane >> 2;             // 0..7
    const int zq = lane & 3;              // 0..3
    const float* __restrict__ swp = s_w[warp];

    float acc[8][4];
#pragma unroll
    for (int i = 0; i < 8; ++i)
#pragma unroll
        for (int j = 0; j < 4; ++j) acc[i][j] = 0.f;

#pragma unroll 2
    for (int p = 0; p < cnt; ++p) {
        const float* s = swp + p * SLICE;
        const float  wy = s[8 + y];                       // 8 distinct
        const float4 wz = *(const float4*)(s + 16 + 4 * zq);  // 64B/warp
        float4 tz;
        tz.x = wy * wz.x; tz.y = wy * wz.y;
        tz.z = wy * wz.z; tz.w = wy * wz.w;
        const float4 wxa = *(const float4*)(s);           // warp-uniform
        const float4 wxb = *(const float4*)(s + 4);       // warp-uniform
        const float wx[8] = { wxa.x, wxa.y, wxa.z, wxa.w,
                              wxb.x, wxb.y, wxb.z, wxb.w };
#pragma unroll
        for (int xx = 0; xx < 8; ++xx) {
            acc[xx][0] = fmaf(wx[xx], tz.x, acc[xx][0]);
            acc[xx][1] = fmaf(wx[xx], tz.y, acc[xx][1]);
            acc[xx][2] = fmaf(wx[xx], tz.z, acc[xx][2]);
            acc[xx][3] = fmaf(wx[xx], tz.w, acc[xx][3]);
        }
    }

    // Stores: per x one STG.128; 4-lane groups write contiguous 64B z-rows.
    float* base = vol + ((size_t)(txi * TSX) * VOLD + (tyi * TSY + y)) * VOLD
                      + tzi * TSZ + 4 * zq;
#pragma unroll
    for (int xx = 0; xx < 8; ++xx) {
        *(float4*)(base + (size_t)xx * VOLD * VOLD) =
            make_float4(acc[xx][0], acc[xx][1], acc[xx][2], acc[xx][3]);
    }
}

// ---------------------------------------------------------------------------
extern "C" void kernel_launch(void* const* d_in, const int* in_sizes, int n_in,
                              void* d_out, int out_size) {
    const float* centers = (const float*)d_in[0];
    const float* sigmas  = (const float*)d_in[1];
    const float* intens  = (const float*)d_in[2];
    float* vol = (float*)d_out;

    prep_kernel<<<NGAUSS, 128>>>(centers, sigmas);
    gather_kernel<<<NTILES / 4, 128>>>(centers, sigmas, intens, vol);
}